// round 2
// baseline (speedup 1.0000x reference)
#include <cuda_runtime.h>
#include <cuda_bf16.h>
#include <cstdint>

// Problem constants
#define NN      50000
#define EE      640000
#define HID     128
#define RR      5
#define NHEADS  8
#define HDIM    16
#define NCOLS   (RR*3*HID)   // 1920
#define LN_EPS  1e-5f

// ---------------- static device scratch (no allocations allowed) ----------------
__device__ float g_wbig[HID * NCOLS];              // 128 x 1920 packed QKV weights
__device__ float g_wproj[HID * HID];               // 128 x 128 transposed out_proj
__device__ float g_qkv[(size_t)NN * NCOLS];        // per (node, relation): [Q 128][K 128][V 128]
__device__ float g_exp[(size_t)EE * NHEADS];       // exp(logit) per edge/head
__device__ float g_sum[NN * RR * NHEADS];          // softmax denominators per (dst, r, head)
__device__ float g_acc[(size_t)NN * HID];          // attention output accumulator
__device__ float g_proj[(size_t)NN * HID];         // out_proj result
__device__ int   g_src[EE];
__device__ int   g_dst[EE];
__device__ int   g_rel[EE];
__device__ int   g_is64;

// ---------------- K-1: detect whether edge_index arrived as int64 or int32 ----------------
// If int64 (values < 50000), every odd 32-bit word is zero. If int32, odd words
// are random node indices (P(zero) ~ 2e-5). Sample 2048 pairs.
__global__ void detect_kernel(const int* __restrict__ ei_raw) {
    if (threadIdx.x == 0 && blockIdx.x == 0) {
        int zeros = 0;
        for (int i = 0; i < 2048; i++) {
            if (ei_raw[2 * i + 1] == 0) zeros++;
        }
        g_is64 = (zeros > 2000) ? 1 : 0;
    }
}

// ---------------- K0a: convert/unpack edge arrays to int32 ----------------
__global__ void convert_kernel(const int* __restrict__ ei_raw,
                               const int* __restrict__ et_raw) {
    int i = blockIdx.x * blockDim.x + threadIdx.x;
    if (i >= EE) return;
    int s, d, r;
    if (g_is64) {
        s = ei_raw[2 * i];
        d = ei_raw[2 * (EE + i)];
        r = et_raw[2 * i];
    } else {
        s = ei_raw[i];
        d = ei_raw[EE + i];
        r = et_raw[i];
    }
    // defensive clamp: wrong dtype guess -> wrong answer (measurable), not IMA
    s = min(max(s, 0), NN - 1);
    d = min(max(d, 0), NN - 1);
    r = min(max(r, 0), RR - 1);
    g_src[i] = s;
    g_dst[i] = d;
    g_rel[i] = r;
}

// ---------------- K0b: zero scratch ----------------
__global__ void zero_kernel() {
    size_t tot1 = (size_t)NN * RR * NHEADS;
    size_t tot2 = (size_t)NN * HID;
    size_t idx = (size_t)blockIdx.x * blockDim.x + threadIdx.x;
    size_t stride = (size_t)gridDim.x * blockDim.x;
    for (size_t i = idx; i < tot1; i += stride) g_sum[i] = 0.0f;
    for (size_t i = idx; i < tot2; i += stride) g_acc[i] = 0.0f;
}

// ---------------- K1: repack weights ----------------
// Wbig[k][c], c = r*384 + t*128 + h*16 + d ; value = W_t[r][h][k][d]
// Wproj[i][j] = out_proj_w[j][i]
__global__ void repack_kernel(const float* __restrict__ WQ,
                              const float* __restrict__ WK,
                              const float* __restrict__ WV,
                              const float* __restrict__ Wp) {
    int idx = blockIdx.x * blockDim.x + threadIdx.x;
    if (idx < HID * NCOLS) {
        int k = idx / NCOLS;
        int c = idx % NCOLS;
        int r = c / 384;
        int rem = c % 384;
        int t = rem / 128;
        int hd = rem % 128;
        int h = hd / HDIM;
        int d = hd % HDIM;
        const float* W = (t == 0) ? WQ : (t == 1) ? WK : WV;
        g_wbig[idx] = W[(((size_t)(r * NHEADS + h) * HID) + k) * HDIM + d];
    }
    if (idx < HID * HID) {
        int i = idx / HID;
        int j = idx % HID;
        g_wproj[idx] = Wp[j * HID + i];
    }
}

// ---------------- tiled fp32 GEMM: C[M x Ncols] = A[M x 128] * B[128 x Ncols] ----------------
// BM=BN=128, BK=32 chunks, 256 threads, 8x8 register tile. Static shared (33KB).
#define BK   32
#define GPAD 132

__device__ __forceinline__ void gemm_body(const float* __restrict__ A,
                                          const float* __restrict__ B,
                                          float* __restrict__ C,
                                          int M, int Ncols) {
    __shared__ float As[BK][GPAD];   // [k][m]
    __shared__ float Bs[BK][GPAD];   // [k][n]

    int tid = threadIdx.x;           // 256
    int tx = tid & 15;
    int ty = tid >> 4;
    int bm = blockIdx.x * 128;
    int bn = blockIdx.y * 128;

    float acc[8][8];
    #pragma unroll
    for (int i = 0; i < 8; i++)
        #pragma unroll
        for (int j = 0; j < 8; j++) acc[i][j] = 0.0f;

    for (int kc = 0; kc < HID; kc += BK) {
        // Load A chunk (transpose into As[k][m]): 128 rows x 32 k = 1024 float4
        #pragma unroll
        for (int j = 0; j < 4; j++) {
            int f = tid + 256 * j;
            int m = f >> 3;            // 0..127
            int c4 = f & 7;            // 0..7 -> k offset c4*4
            int gm = bm + m;
            float4 v = make_float4(0.f, 0.f, 0.f, 0.f);
            if (gm < M) v = *(const float4*)(A + (size_t)gm * HID + kc + c4 * 4);
            As[c4 * 4 + 0][m] = v.x;
            As[c4 * 4 + 1][m] = v.y;
            As[c4 * 4 + 2][m] = v.z;
            As[c4 * 4 + 3][m] = v.w;
        }
        // Load B chunk: 32 k x 128 n = 1024 float4
        #pragma unroll
        for (int j = 0; j < 4; j++) {
            int f = tid + 256 * j;
            int k = f >> 5;            // 0..31
            int c4 = f & 31;           // 0..31 -> n offset c4*4
            float4 v = *(const float4*)(B + (size_t)(kc + k) * Ncols + bn + c4 * 4);
            *(float4*)(&Bs[k][c4 * 4]) = v;
        }
        __syncthreads();

        #pragma unroll
        for (int k = 0; k < BK; k++) {
            float a[8], b[8];
            *(float4*)(a)     = *(float4*)(&As[k][ty * 8]);
            *(float4*)(a + 4) = *(float4*)(&As[k][ty * 8 + 4]);
            *(float4*)(b)     = *(float4*)(&Bs[k][tx * 8]);
            *(float4*)(b + 4) = *(float4*)(&Bs[k][tx * 8 + 4]);
            #pragma unroll
            for (int i = 0; i < 8; i++)
                #pragma unroll
                for (int j = 0; j < 8; j++)
                    acc[i][j] = fmaf(a[i], b[j], acc[i][j]);
        }
        __syncthreads();
    }

    #pragma unroll
    for (int i = 0; i < 8; i++) {
        int gm = bm + ty * 8 + i;
        if (gm < M) {
            float* dst = C + (size_t)gm * Ncols + bn + tx * 8;
            *(float4*)(dst)     = *(float4*)(&acc[i][0]);
            *(float4*)(dst + 4) = *(float4*)(&acc[i][4]);
        }
    }
}

__global__ void __launch_bounds__(256) gemm_qkv_kernel(const float* __restrict__ A) {
    gemm_body(A, g_wbig, g_qkv, NN, NCOLS);
}
__global__ void __launch_bounds__(256) gemm_proj_kernel() {
    gemm_body(g_acc, g_wproj, g_proj, NN, HID);
}

// ---------------- K3: per-edge logits + exp + denominator accumulation ----------------
// warp per edge; lane l handles dims [4l, 4l+4); head = l/4
__global__ void edge_logits_kernel(const float* __restrict__ bias) {
    int w = (blockIdx.x * blockDim.x + threadIdx.x) >> 5;
    int l = threadIdx.x & 31;
    if (w >= EE) return;
    int src = g_src[w];
    int dst = g_dst[w];
    int r = g_rel[w];

    const float* qb = g_qkv + ((size_t)dst * RR + r) * 384;          // Q(dst)
    const float* kb = g_qkv + ((size_t)src * RR + r) * 384 + 128;    // K(src)
    float4 q = *(const float4*)(qb + l * 4);
    float4 k = *(const float4*)(kb + l * 4);
    float p = q.x * k.x + q.y * k.y + q.z * k.z + q.w * k.w;
    p += __shfl_xor_sync(0xFFFFFFFFu, p, 1);
    p += __shfl_xor_sync(0xFFFFFFFFu, p, 2);
    int h = l >> 2;
    float logit = p * 0.25f + bias[r * NHEADS + h];   // scale = sqrt(16) = 4
    float ev = expf(logit);                            // softmax max-sub is removable
    if ((l & 3) == 0) {
        g_exp[(size_t)w * NHEADS + h] = ev;
        atomicAdd(&g_sum[(dst * RR + r) * NHEADS + h], ev);
    }
}

// ---------------- K4: per-edge attn * V accumulation ----------------
__global__ void edge_accum_kernel() {
    int w = (blockIdx.x * blockDim.x + threadIdx.x) >> 5;
    int l = threadIdx.x & 31;
    if (w >= EE) return;
    int src = g_src[w];
    int dst = g_dst[w];
    int r = g_rel[w];
    int h = l >> 2;

    float ev = g_exp[(size_t)w * NHEADS + h];
    float s = g_sum[(dst * RR + r) * NHEADS + h];
    float attn = ev / (s + 1e-12f);

    const float* vb = g_qkv + ((size_t)src * RR + r) * 384 + 256;    // V(src)
    float4 v = *(const float4*)(vb + l * 4);
    float* ob = g_acc + (size_t)dst * HID + l * 4;
    atomicAdd(ob + 0, attn * v.x);
    atomicAdd(ob + 1, attn * v.y);
    atomicAdd(ob + 2, attn * v.z);
    atomicAdd(ob + 3, attn * v.w);
}

// ---------------- K6: bias + residual + LayerNorm (warp per node) ----------------
__global__ void ln_kernel(const float* __restrict__ x,
                          const float* __restrict__ pb,
                          const float* __restrict__ gamma,
                          const float* __restrict__ beta,
                          float* __restrict__ out) {
    int n = (blockIdx.x * blockDim.x + threadIdx.x) >> 5;
    int l = threadIdx.x & 31;
    if (n >= NN) return;
    size_t base = (size_t)n * HID + l * 4;

    float4 p = *(const float4*)(g_proj + base);
    float4 xx = *(const float4*)(x + base);
    float4 b = *(const float4*)(pb + l * 4);
    float4 h;
    h.x = p.x + b.x + xx.x;
    h.y = p.y + b.y + xx.y;
    h.z = p.z + b.z + xx.z;
    h.w = p.w + b.w + xx.w;

    float s = h.x + h.y + h.z + h.w;
    #pragma unroll
    for (int off = 16; off >= 1; off >>= 1) s += __shfl_xor_sync(0xFFFFFFFFu, s, off);
    float mu = s * (1.0f / HID);

    float dx = h.x - mu, dy = h.y - mu, dz = h.z - mu, dw = h.w - mu;
    float v = dx * dx + dy * dy + dz * dz + dw * dw;
    #pragma unroll
    for (int off = 16; off >= 1; off >>= 1) v += __shfl_xor_sync(0xFFFFFFFFu, v, off);
    float inv = rsqrtf(v * (1.0f / HID) + LN_EPS);

    float4 g = *(const float4*)(gamma + l * 4);
    float4 be = *(const float4*)(beta + l * 4);
    float4 o;
    o.x = dx * inv * g.x + be.x;
    o.y = dy * inv * g.y + be.y;
    o.z = dz * inv * g.z + be.z;
    o.w = dw * inv * g.w + be.w;
    *(float4*)(out + base) = o;
}

// ---------------- launch ----------------
extern "C" void kernel_launch(void* const* d_in, const int* in_sizes, int n_in,
                              void* d_out, int out_size) {
    const float* x     = (const float*)d_in[0];
    const int*   ei    = (const int*)d_in[1];   // int32 or packed int64 (auto-detected)
    const int*   et    = (const int*)d_in[2];
    const float* WQ    = (const float*)d_in[3];
    const float* WK    = (const float*)d_in[4];
    const float* WV    = (const float*)d_in[5];
    const float* bias  = (const float*)d_in[6];
    const float* Wp    = (const float*)d_in[7];
    const float* pb    = (const float*)d_in[8];
    const float* gamma = (const float*)d_in[9];
    const float* beta  = (const float*)d_in[10];
    float* out = (float*)d_out;

    detect_kernel<<<1, 32>>>(ei);
    convert_kernel<<<(EE + 255) / 256, 256>>>(ei, et);
    zero_kernel<<<1024, 256>>>();
    repack_kernel<<<(HID * NCOLS + 255) / 256, 256>>>(WQ, WK, WV, Wp);

    dim3 g1((NN + 127) / 128, NCOLS / 128);   // 391 x 15
    gemm_qkv_kernel<<<g1, 256>>>(x);

    int edge_blocks = (EE * 32 + 255) / 256;  // 80000
    edge_logits_kernel<<<edge_blocks, 256>>>(bias);
    edge_accum_kernel<<<edge_blocks, 256>>>();

    dim3 g2((NN + 127) / 128, 1);             // 391 x 1
    gemm_proj_kernel<<<g2, 256>>>();

    int ln_blocks = (NN * 32 + 255) / 256;    // 6250
    ln_kernel<<<ln_blocks, 256>>>(x, pb, gamma, beta, out);
}

// round 3
// speedup vs baseline: 1.0116x; 1.0116x over previous
#include <cuda_runtime.h>
#include <cuda_bf16.h>
#include <cstdint>

// Problem constants
#define NN      50000
#define EE      640000
#define HID     128
#define RR      5
#define NHEADS  8
#define HDIM    16
#define NCOLS   (RR*3*HID)   // 1920
#define LN_EPS  1e-5f

// ---------------- static device scratch (no allocations allowed) ----------------
__device__ float g_wbig[HID * NCOLS];              // 128 x 1920 packed QKV weights
__device__ float g_wproj[HID * HID];               // 128 x 128 transposed out_proj
__device__ float g_qkv[(size_t)NN * NCOLS];        // per (node, relation): [Q 128][K 128][V 128]
__device__ float g_exp[(size_t)EE * NHEADS];       // exp(logit) per edge/head
__device__ float g_sum[NN * RR * NHEADS];          // softmax denominators per (dst, r, head)
__device__ float g_acc[(size_t)NN * HID];          // attention output accumulator
__device__ float g_proj[(size_t)NN * HID];         // out_proj result
__device__ int   g_src[EE];
__device__ int   g_dst[EE];
__device__ int   g_rel[EE];
__device__ int   g_is64;
// CSR-by-dst sort scratch
__device__ int   g_cnt[NN];
__device__ int   g_off[NN + 1];
__device__ int   g_cur[NN];
__device__ int   g_eid[EE];

// ---------------- K-1: detect whether edge_index arrived as int64 or int32 ----------------
__global__ void detect_kernel(const int* __restrict__ ei_raw) {
    if (threadIdx.x == 0 && blockIdx.x == 0) {
        int zeros = 0;
        for (int i = 0; i < 2048; i++) {
            if (ei_raw[2 * i + 1] == 0) zeros++;
        }
        g_is64 = (zeros > 2000) ? 1 : 0;
    }
}

// ---------------- K0a: convert/unpack edge arrays to int32 ----------------
__global__ void convert_kernel(const int* __restrict__ ei_raw,
                               const int* __restrict__ et_raw) {
    int i = blockIdx.x * blockDim.x + threadIdx.x;
    if (i >= EE) return;
    int s, d, r;
    if (g_is64) {
        s = ei_raw[2 * i];
        d = ei_raw[2 * (EE + i)];
        r = et_raw[2 * i];
    } else {
        s = ei_raw[i];
        d = ei_raw[EE + i];
        r = et_raw[i];
    }
    s = min(max(s, 0), NN - 1);
    d = min(max(d, 0), NN - 1);
    r = min(max(r, 0), RR - 1);
    g_src[i] = s;
    g_dst[i] = d;
    g_rel[i] = r;
}

// ---------------- K0b: zero scratch (g_sum + histogram counters) ----------------
__global__ void zero_kernel() {
    size_t tot1 = (size_t)NN * RR * NHEADS;
    size_t idx = (size_t)blockIdx.x * blockDim.x + threadIdx.x;
    size_t stride = (size_t)gridDim.x * blockDim.x;
    for (size_t i = idx; i < tot1; i += stride) g_sum[i] = 0.0f;
    for (size_t i = idx; i < NN; i += stride) g_cnt[i] = 0;
}

// ---------------- K0c/d/e: counting sort of edges by dst ----------------
__global__ void hist_kernel() {
    int i = blockIdx.x * blockDim.x + threadIdx.x;
    if (i < EE) atomicAdd(&g_cnt[g_dst[i]], 1);
}

// single-block exclusive scan over 50000 counters
__global__ void scan_kernel() {
    __shared__ int s[1024];
    const int T = 1024;
    const int CH = (NN + T - 1) / T;   // 49
    int t = threadIdx.x;
    int base = t * CH;
    int sum = 0;
    for (int i = 0; i < CH; i++) {
        int idx = base + i;
        if (idx < NN) sum += g_cnt[idx];
    }
    s[t] = sum;
    __syncthreads();
    // inclusive Hillis-Steele scan
    for (int off = 1; off < T; off <<= 1) {
        int v = (t >= off) ? s[t - off] : 0;
        __syncthreads();
        s[t] += v;
        __syncthreads();
    }
    int run = (t == 0) ? 0 : s[t - 1];
    for (int i = 0; i < CH; i++) {
        int idx = base + i;
        if (idx < NN) {
            g_off[idx] = run;
            g_cur[idx] = run;
            run += g_cnt[idx];
        }
    }
    if (t == 0) g_off[NN] = EE;
}

__global__ void scatter_kernel() {
    int i = blockIdx.x * blockDim.x + threadIdx.x;
    if (i < EE) {
        int pos = atomicAdd(&g_cur[g_dst[i]], 1);
        g_eid[pos] = i;
    }
}

// ---------------- K1: repack weights ----------------
__global__ void repack_kernel(const float* __restrict__ WQ,
                              const float* __restrict__ WK,
                              const float* __restrict__ WV,
                              const float* __restrict__ Wp) {
    int idx = blockIdx.x * blockDim.x + threadIdx.x;
    if (idx < HID * NCOLS) {
        int k = idx / NCOLS;
        int c = idx % NCOLS;
        int r = c / 384;
        int rem = c % 384;
        int t = rem / 128;
        int hd = rem % 128;
        int h = hd / HDIM;
        int d = hd % HDIM;
        const float* W = (t == 0) ? WQ : (t == 1) ? WK : WV;
        g_wbig[idx] = W[(((size_t)(r * NHEADS + h) * HID) + k) * HDIM + d];
    }
    if (idx < HID * HID) {
        int i = idx / HID;
        int j = idx % HID;
        g_wproj[idx] = Wp[j * HID + i];
    }
}

// ---------------- tiled fp32 GEMM with packed fma.rn.f32x2 ----------------
// C[M x Ncols] = A[M x 128] * B[128 x Ncols]
// BM=BN=128, BK=32, 256 threads, 8x8 register tile held as 8x4 packed f32x2.
#define BK   32
#define GPAD 132

#define FMA2(accv, a2, b2) \
    asm("fma.rn.f32x2 %0, %1, %2, %0;" : "+l"(accv) : "l"(a2), "l"(b2))
#define PACK_DUP(dst64, fval) \
    asm("mov.b64 %0, {%1, %1};" : "=l"(dst64) : "f"(fval))

__device__ __forceinline__ void gemm_body(const float* __restrict__ A,
                                          const float* __restrict__ B,
                                          float* __restrict__ C,
                                          int M, int Ncols) {
    __shared__ float As[BK][GPAD];   // [k][m]
    __shared__ float Bs[BK][GPAD];   // [k][n]

    int tid = threadIdx.x;           // 256
    int tx = tid & 15;
    int ty = tid >> 4;
    int bm = blockIdx.x * 128;
    int bn = blockIdx.y * 128;

    unsigned long long accp[8][4];
    #pragma unroll
    for (int i = 0; i < 8; i++)
        #pragma unroll
        for (int j = 0; j < 4; j++) accp[i][j] = 0ULL;

    for (int kc = 0; kc < HID; kc += BK) {
        // Load A chunk (transpose into As[k][m])
        #pragma unroll
        for (int j = 0; j < 4; j++) {
            int f = tid + 256 * j;
            int m = f >> 3;            // 0..127
            int c4 = f & 7;            // k offset = c4*4
            int gm = bm + m;
            float4 v = make_float4(0.f, 0.f, 0.f, 0.f);
            if (gm < M) v = *(const float4*)(A + (size_t)gm * HID + kc + c4 * 4);
            As[c4 * 4 + 0][m] = v.x;
            As[c4 * 4 + 1][m] = v.y;
            As[c4 * 4 + 2][m] = v.z;
            As[c4 * 4 + 3][m] = v.w;
        }
        // Load B chunk (row-major direct)
        #pragma unroll
        for (int j = 0; j < 4; j++) {
            int f = tid + 256 * j;
            int k = f >> 5;            // 0..31
            int c4 = f & 31;           // n offset = c4*4
            float4 v = *(const float4*)(B + (size_t)(kc + k) * Ncols + bn + c4 * 4);
            *(float4*)(&Bs[k][c4 * 4]) = v;
        }
        __syncthreads();

        #pragma unroll 8
        for (int k = 0; k < BK; k++) {
            float a[8];
            unsigned long long bp[4];
            *(float4*)(a)     = *(float4*)(&As[k][ty * 8]);
            *(float4*)(a + 4) = *(float4*)(&As[k][ty * 8 + 4]);
            bp[0] = *(const unsigned long long*)(&Bs[k][tx * 8 + 0]);
            bp[1] = *(const unsigned long long*)(&Bs[k][tx * 8 + 2]);
            bp[2] = *(const unsigned long long*)(&Bs[k][tx * 8 + 4]);
            bp[3] = *(const unsigned long long*)(&Bs[k][tx * 8 + 6]);
            #pragma unroll
            for (int i = 0; i < 8; i++) {
                unsigned long long ad;
                PACK_DUP(ad, a[i]);
                #pragma unroll
                for (int j = 0; j < 4; j++)
                    FMA2(accp[i][j], ad, bp[j]);
            }
        }
        __syncthreads();
    }

    #pragma unroll
    for (int i = 0; i < 8; i++) {
        int gm = bm + ty * 8 + i;
        if (gm < M) {
            float* dst = C + (size_t)gm * Ncols + bn + tx * 8;
            *(float4*)(dst)     = *(float4*)(&accp[i][0]);
            *(float4*)(dst + 4) = *(float4*)(&accp[i][2]);
        }
    }
}

__global__ void __launch_bounds__(256) gemm_qkv_kernel(const float* __restrict__ A) {
    gemm_body(A, g_wbig, g_qkv, NN, NCOLS);
}
__global__ void __launch_bounds__(256) gemm_proj_kernel() {
    gemm_body(g_acc, g_wproj, g_proj, NN, HID);
}

// ---------------- K3: per-edge logits + exp + denominator accumulation ----------------
// warp per edge; lane l handles dims [4l, 4l+4); head = l/4
__global__ void edge_logits_kernel(const float* __restrict__ bias) {
    int w = (blockIdx.x * blockDim.x + threadIdx.x) >> 5;
    int l = threadIdx.x & 31;
    if (w >= EE) return;
    int src = g_src[w];
    int dst = g_dst[w];
    int r = g_rel[w];

    const float* qb = g_qkv + ((size_t)dst * RR + r) * 384;          // Q(dst)
    const float* kb = g_qkv + ((size_t)src * RR + r) * 384 + 128;    // K(src)
    float4 q = *(const float4*)(qb + l * 4);
    float4 k = *(const float4*)(kb + l * 4);
    float p = q.x * k.x + q.y * k.y + q.z * k.z + q.w * k.w;
    p += __shfl_xor_sync(0xFFFFFFFFu, p, 1);
    p += __shfl_xor_sync(0xFFFFFFFFu, p, 2);
    int h = l >> 2;
    float logit = p * 0.25f + bias[r * NHEADS + h];   // scale = sqrt(16) = 4
    float ev = expf(logit);                            // softmax max-sub is removable
    if ((l & 3) == 0) {
        g_exp[(size_t)w * NHEADS + h] = ev;
        atomicAdd(&g_sum[(dst * RR + r) * NHEADS + h], ev);
    }
}

// ---------------- K4: segmented attn*V accumulation (warp per dst, no atomics) ----------------
__global__ void seg_accum_kernel() {
    int n = (blockIdx.x * blockDim.x + threadIdx.x) >> 5;
    int l = threadIdx.x & 31;
    if (n >= NN) return;
    int h = l >> 2;   // dims [4l,4l+4) all belong to head l/4

    // preload softmax reciprocals for this (dst, head) over all relations
    float inv_s[RR];
    #pragma unroll
    for (int r = 0; r < RR; r++) {
        float s = g_sum[((size_t)n * RR + r) * NHEADS + h];
        inv_s[r] = 1.0f / (s + 1e-12f);
    }

    float4 acc = make_float4(0.f, 0.f, 0.f, 0.f);
    int e0 = g_off[n];
    int e1 = g_off[n + 1];
    #pragma unroll 4
    for (int e = e0; e < e1; e++) {
        int eid = g_eid[e];
        int r = g_rel[eid];
        int src = g_src[eid];
        float attn = g_exp[(size_t)eid * NHEADS + h] * inv_s[r];
        const float4 v = *(const float4*)(g_qkv + ((size_t)src * RR + r) * 384 + 256 + l * 4);
        acc.x += attn * v.x;
        acc.y += attn * v.y;
        acc.z += attn * v.z;
        acc.w += attn * v.w;
    }
    *(float4*)(g_acc + (size_t)n * HID + l * 4) = acc;
}

// ---------------- K6: bias + residual + LayerNorm (warp per node) ----------------
__global__ void ln_kernel(const float* __restrict__ x,
                          const float* __restrict__ pb,
                          const float* __restrict__ gamma,
                          const float* __restrict__ beta,
                          float* __restrict__ out) {
    int n = (blockIdx.x * blockDim.x + threadIdx.x) >> 5;
    int l = threadIdx.x & 31;
    if (n >= NN) return;
    size_t base = (size_t)n * HID + l * 4;

    float4 p = *(const float4*)(g_proj + base);
    float4 xx = *(const float4*)(x + base);
    float4 b = *(const float4*)(pb + l * 4);
    float4 h;
    h.x = p.x + b.x + xx.x;
    h.y = p.y + b.y + xx.y;
    h.z = p.z + b.z + xx.z;
    h.w = p.w + b.w + xx.w;

    float s = h.x + h.y + h.z + h.w;
    #pragma unroll
    for (int off = 16; off >= 1; off >>= 1) s += __shfl_xor_sync(0xFFFFFFFFu, s, off);
    float mu = s * (1.0f / HID);

    float dx = h.x - mu, dy = h.y - mu, dz = h.z - mu, dw = h.w - mu;
    float v = dx * dx + dy * dy + dz * dz + dw * dw;
    #pragma unroll
    for (int off = 16; off >= 1; off >>= 1) v += __shfl_xor_sync(0xFFFFFFFFu, v, off);
    float inv = rsqrtf(v * (1.0f / HID) + LN_EPS);

    float4 g = *(const float4*)(gamma + l * 4);
    float4 be = *(const float4*)(beta + l * 4);
    float4 o;
    o.x = dx * inv * g.x + be.x;
    o.y = dy * inv * g.y + be.y;
    o.z = dz * inv * g.z + be.z;
    o.w = dw * inv * g.w + be.w;
    *(float4*)(out + base) = o;
}

// ---------------- launch ----------------
extern "C" void kernel_launch(void* const* d_in, const int* in_sizes, int n_in,
                              void* d_out, int out_size) {
    const float* x     = (const float*)d_in[0];
    const int*   ei    = (const int*)d_in[1];   // int32 or packed int64 (auto-detected)
    const int*   et    = (const int*)d_in[2];
    const float* WQ    = (const float*)d_in[3];
    const float* WK    = (const float*)d_in[4];
    const float* WV    = (const float*)d_in[5];
    const float* bias  = (const float*)d_in[6];
    const float* Wp    = (const float*)d_in[7];
    const float* pb    = (const float*)d_in[8];
    const float* gamma = (const float*)d_in[9];
    const float* beta  = (const float*)d_in[10];
    float* out = (float*)d_out;

    detect_kernel<<<1, 32>>>(ei);
    convert_kernel<<<(EE + 255) / 256, 256>>>(ei, et);
    zero_kernel<<<1024, 256>>>();
    repack_kernel<<<(HID * NCOLS + 255) / 256, 256>>>(WQ, WK, WV, Wp);

    // counting sort of edges by dst
    hist_kernel<<<(EE + 255) / 256, 256>>>();
    scan_kernel<<<1, 1024>>>();
    scatter_kernel<<<(EE + 255) / 256, 256>>>();

    dim3 g1((NN + 127) / 128, NCOLS / 128);   // 391 x 15
    gemm_qkv_kernel<<<g1, 256>>>(x);

    int edge_blocks = (EE * 32 + 255) / 256;  // 80000
    edge_logits_kernel<<<edge_blocks, 256>>>(bias);

    int seg_blocks = (NN * 32 + 255) / 256;   // 6250
    seg_accum_kernel<<<seg_blocks, 256>>>();

    dim3 g2((NN + 127) / 128, 1);             // 391 x 1
    gemm_proj_kernel<<<g2, 256>>>();

    int ln_blocks = (NN * 32 + 255) / 256;    // 6250
    ln_kernel<<<ln_blocks, 256>>>(x, pb, gamma, beta, out);
}

// round 4
// speedup vs baseline: 1.2035x; 1.1897x over previous
#include <cuda_runtime.h>
#include <cuda_bf16.h>
#include <mma.h>
#include <cstdint>

using namespace nvcuda;

// Problem constants
#define NN      50000
#define NN_PAD  50048            // 128 * 391, pad so wmma stores need no tail mask
#define EE      640000
#define HID     128
#define RR      5
#define NHEADS  8
#define HDIM    16
#define NCOLS   (RR*3*HID)       // 1920
#define LN_EPS  1e-5f

// ---------------- static device scratch (no allocations allowed) ----------------
__device__ float g_wbig[HID * NCOLS];                // 128 x 1920 packed QKV weights
__device__ float g_wproj[HID * HID];                 // 128 x 128 transposed out_proj
__device__ float g_qkv[(size_t)NN_PAD * NCOLS];      // per (node, relation): [Q 128][K 128][V 128]
__device__ float g_exp[(size_t)EE * NHEADS];         // exp(logit) per edge/head
__device__ float g_sum[NN * RR * NHEADS];            // softmax denominators per (dst, r, head)
__device__ float g_acc[(size_t)NN * HID];            // attention output accumulator
__device__ float g_proj[(size_t)NN_PAD * HID];       // out_proj result (padded rows)
__device__ int   g_src[EE];
__device__ int   g_dst[EE];
__device__ int   g_rel[EE];
__device__ int   g_is64;
// CSR-by-dst sort scratch
__device__ int   g_cnt[NN];
__device__ int   g_off[NN + 1];
__device__ int   g_cur[NN];
__device__ int   g_eid[EE];

// ---------------- K-1: detect int64 vs int32 edge_index (parallel, MLP-friendly) ----------------
// If int64 (values < 50000), every odd 32-bit word is zero.
__global__ void detect_kernel(const int* __restrict__ ei_raw) {
    int l = threadIdx.x;           // 32 threads
    int zeros = 0;
    #pragma unroll
    for (int j = 0; j < 16; j++) {
        int i = l * 16 + j;        // 512 samples
        if (ei_raw[2 * i + 1] == 0) zeros++;
    }
    #pragma unroll
    for (int off = 16; off >= 1; off >>= 1)
        zeros += __shfl_xor_sync(0xFFFFFFFFu, zeros, off);
    if (l == 0) g_is64 = (zeros > 500) ? 1 : 0;
}

// ---------------- K0a: convert/unpack edge arrays to int32 ----------------
__global__ void convert_kernel(const int* __restrict__ ei_raw,
                               const int* __restrict__ et_raw) {
    int i = blockIdx.x * blockDim.x + threadIdx.x;
    if (i >= EE) return;
    int s, d, r;
    if (g_is64) {
        s = ei_raw[2 * i];
        d = ei_raw[2 * (EE + i)];
        r = et_raw[2 * i];
    } else {
        s = ei_raw[i];
        d = ei_raw[EE + i];
        r = et_raw[i];
    }
    s = min(max(s, 0), NN - 1);
    d = min(max(d, 0), NN - 1);
    r = min(max(r, 0), RR - 1);
    g_src[i] = s;
    g_dst[i] = d;
    g_rel[i] = r;
}

// ---------------- K0b: zero scratch (g_sum + histogram counters) ----------------
__global__ void zero_kernel() {
    size_t tot1 = (size_t)NN * RR * NHEADS;
    size_t idx = (size_t)blockIdx.x * blockDim.x + threadIdx.x;
    size_t stride = (size_t)gridDim.x * blockDim.x;
    for (size_t i = idx; i < tot1; i += stride) g_sum[i] = 0.0f;
    for (size_t i = idx; i < NN; i += stride) g_cnt[i] = 0;
}

// ---------------- K0c/d/e: counting sort of edges by dst ----------------
__global__ void hist_kernel() {
    int i = blockIdx.x * blockDim.x + threadIdx.x;
    if (i < EE) atomicAdd(&g_cnt[g_dst[i]], 1);
}

__global__ void scan_kernel() {
    __shared__ int s[1024];
    const int T = 1024;
    const int CH = (NN + T - 1) / T;   // 49
    int t = threadIdx.x;
    int base = t * CH;
    int sum = 0;
    for (int i = 0; i < CH; i++) {
        int idx = base + i;
        if (idx < NN) sum += g_cnt[idx];
    }
    s[t] = sum;
    __syncthreads();
    for (int off = 1; off < T; off <<= 1) {
        int v = (t >= off) ? s[t - off] : 0;
        __syncthreads();
        s[t] += v;
        __syncthreads();
    }
    int run = (t == 0) ? 0 : s[t - 1];
    for (int i = 0; i < CH; i++) {
        int idx = base + i;
        if (idx < NN) {
            g_off[idx] = run;
            g_cur[idx] = run;
            run += g_cnt[idx];
        }
    }
    if (t == 0) g_off[NN] = EE;
}

__global__ void scatter_kernel() {
    int i = blockIdx.x * blockDim.x + threadIdx.x;
    if (i < EE) {
        int pos = atomicAdd(&g_cur[g_dst[i]], 1);
        g_eid[pos] = i;
    }
}

// ---------------- K1: repack weights ----------------
__global__ void repack_kernel(const float* __restrict__ WQ,
                              const float* __restrict__ WK,
                              const float* __restrict__ WV,
                              const float* __restrict__ Wp) {
    int idx = blockIdx.x * blockDim.x + threadIdx.x;
    if (idx < HID * NCOLS) {
        int k = idx / NCOLS;
        int c = idx % NCOLS;
        int r = c / 384;
        int rem = c % 384;
        int t = rem / 128;
        int hd = rem % 128;
        int h = hd / HDIM;
        int d = hd % HDIM;
        const float* W = (t == 0) ? WQ : (t == 1) ? WK : WV;
        g_wbig[idx] = W[(((size_t)(r * NHEADS + h) * HID) + k) * HDIM + d];
    }
    if (idx < HID * HID) {
        int i = idx / HID;
        int j = idx % HID;
        g_wproj[idx] = Wp[j * HID + i];
    }
}

// ---------------- tensor-core tf32 GEMM: C[M_pad x Ncols] = A[M x 128] * B[128 x Ncols] ----------------
// CTA tile 128x128, 8 warps as 4(M) x 2(N), warp tile 32x64.
// wmma m16n16k8 tf32, fp32 accumulate. K chunks of 32 in static smem.
#define BK    32
#define A_LD  36      // padded leading dim for As[m][k]
#define B_LD  132     // padded leading dim for Bs[k][n]

__device__ __forceinline__ void gemm_tc_body(const float* __restrict__ A,
                                             const float* __restrict__ B,
                                             float* __restrict__ C,
                                             int M, int Ncols) {
    __shared__ float As[128 * A_LD];   // [m][k]  16.1KB... 128*36*4 = 18KB
    __shared__ float Bs[BK * B_LD];    // [k][n]  32*132*4 = 16.9KB

    int tid = threadIdx.x;             // 256
    int wid = tid >> 5;
    int wm = wid & 3;                  // warp row (M)
    int wn = wid >> 2;                 // warp col (N)
    int bm = blockIdx.x * 128;
    int bn = blockIdx.y * 128;

    wmma::fragment<wmma::accumulator, 16, 16, 8, float> cfrag[2][4];
    #pragma unroll
    for (int i = 0; i < 2; i++)
        #pragma unroll
        for (int j = 0; j < 4; j++)
            wmma::fill_fragment(cfrag[i][j], 0.0f);

    for (int kc = 0; kc < HID; kc += BK) {
        // Load A chunk row-major [m][k]: 128 rows x 32 k = 1024 float4
        #pragma unroll
        for (int j = 0; j < 4; j++) {
            int f = tid + 256 * j;
            int m = f >> 3;            // 0..127
            int c4 = f & 7;            // k offset = c4*4
            int gm = bm + m;
            float4 v = make_float4(0.f, 0.f, 0.f, 0.f);
            if (gm < M) v = *(const float4*)(A + (size_t)gm * HID + kc + c4 * 4);
            *(float4*)(&As[m * A_LD + c4 * 4]) = v;
        }
        // Load B chunk row-major [k][n]: 32 k x 128 n = 1024 float4
        #pragma unroll
        for (int j = 0; j < 4; j++) {
            int f = tid + 256 * j;
            int k = f >> 5;            // 0..31
            int c4 = f & 31;           // n offset = c4*4
            float4 v = *(const float4*)(B + (size_t)(kc + k) * Ncols + bn + c4 * 4);
            *(float4*)(&Bs[k * B_LD + c4 * 4]) = v;
        }
        __syncthreads();

        #pragma unroll
        for (int ks = 0; ks < BK; ks += 8) {
            wmma::fragment<wmma::matrix_a, 16, 16, 8, wmma::precision::tf32, wmma::row_major> afrag[2];
            wmma::fragment<wmma::matrix_b, 16, 16, 8, wmma::precision::tf32, wmma::row_major> bfrag[4];
            #pragma unroll
            for (int i = 0; i < 2; i++) {
                wmma::load_matrix_sync(afrag[i], &As[(wm * 32 + i * 16) * A_LD + ks], A_LD);
                #pragma unroll
                for (int e = 0; e < afrag[i].num_elements; e++)
                    afrag[i].x[e] = wmma::__float_to_tf32(afrag[i].x[e]);
            }
            #pragma unroll
            for (int j = 0; j < 4; j++) {
                wmma::load_matrix_sync(bfrag[j], &Bs[ks * B_LD + wn * 64 + j * 16], B_LD);
                #pragma unroll
                for (int e = 0; e < bfrag[j].num_elements; e++)
                    bfrag[j].x[e] = wmma::__float_to_tf32(bfrag[j].x[e]);
            }
            #pragma unroll
            for (int i = 0; i < 2; i++)
                #pragma unroll
                for (int j = 0; j < 4; j++)
                    wmma::mma_sync(cfrag[i][j], afrag[i], bfrag[j], cfrag[i][j]);
        }
        __syncthreads();
    }

    // Store (C rows padded to a multiple of 128, no tail masking needed)
    #pragma unroll
    for (int i = 0; i < 2; i++) {
        int gm = bm + wm * 32 + i * 16;
        #pragma unroll
        for (int j = 0; j < 4; j++) {
            int gn = bn + wn * 64 + j * 16;
            wmma::store_matrix_sync(C + (size_t)gm * Ncols + gn, cfrag[i][j],
                                    Ncols, wmma::mem_row_major);
        }
    }
}

__global__ void __launch_bounds__(256) gemm_qkv_kernel(const float* __restrict__ A) {
    gemm_tc_body(A, g_wbig, g_qkv, NN, NCOLS);
}
__global__ void __launch_bounds__(256) gemm_proj_kernel() {
    gemm_tc_body(g_acc, g_wproj, g_proj, NN, HID);
}

// ---------------- K3: per-edge logits + exp + denominator accumulation ----------------
// warp per edge; lane l handles dims [4l, 4l+4); head = l/4
__global__ void edge_logits_kernel(const float* __restrict__ bias) {
    int w = (blockIdx.x * blockDim.x + threadIdx.x) >> 5;
    int l = threadIdx.x & 31;
    if (w >= EE) return;
    int src = g_src[w];
    int dst = g_dst[w];
    int r = g_rel[w];

    const float* qb = g_qkv + ((size_t)dst * RR + r) * 384;          // Q(dst)
    const float* kb = g_qkv + ((size_t)src * RR + r) * 384 + 128;    // K(src)
    float4 q = *(const float4*)(qb + l * 4);
    float4 k = *(const float4*)(kb + l * 4);
    float p = q.x * k.x + q.y * k.y + q.z * k.z + q.w * k.w;
    p += __shfl_xor_sync(0xFFFFFFFFu, p, 1);
    p += __shfl_xor_sync(0xFFFFFFFFu, p, 2);
    int h = l >> 2;
    float logit = p * 0.25f + bias[r * NHEADS + h];   // scale = sqrt(16) = 4
    float ev = expf(logit);                            // softmax max-sub is removable
    if ((l & 3) == 0) {
        g_exp[(size_t)w * NHEADS + h] = ev;
        atomicAdd(&g_sum[(dst * RR + r) * NHEADS + h], ev);
    }
}

// ---------------- K4: segmented attn*V accumulation (warp per dst, no atomics) ----------------
__global__ void seg_accum_kernel() {
    int n = (blockIdx.x * blockDim.x + threadIdx.x) >> 5;
    int l = threadIdx.x & 31;
    if (n >= NN) return;
    int h = l >> 2;

    float inv_s[RR];
    #pragma unroll
    for (int r = 0; r < RR; r++) {
        float s = g_sum[((size_t)n * RR + r) * NHEADS + h];
        inv_s[r] = 1.0f / (s + 1e-12f);
    }

    float4 acc = make_float4(0.f, 0.f, 0.f, 0.f);
    int e0 = g_off[n];
    int e1 = g_off[n + 1];
    #pragma unroll 4
    for (int e = e0; e < e1; e++) {
        int eid = g_eid[e];
        int r = g_rel[eid];
        int src = g_src[eid];
        float attn = g_exp[(size_t)eid * NHEADS + h] * inv_s[r];
        const float4 v = *(const float4*)(g_qkv + ((size_t)src * RR + r) * 384 + 256 + l * 4);
        acc.x += attn * v.x;
        acc.y += attn * v.y;
        acc.z += attn * v.z;
        acc.w += attn * v.w;
    }
    *(float4*)(g_acc + (size_t)n * HID + l * 4) = acc;
}

// ---------------- K6: bias + residual + LayerNorm (warp per node) ----------------
__global__ void ln_kernel(const float* __restrict__ x,
                          const float* __restrict__ pb,
                          const float* __restrict__ gamma,
                          const float* __restrict__ beta,
                          float* __restrict__ out) {
    int n = (blockIdx.x * blockDim.x + threadIdx.x) >> 5;
    int l = threadIdx.x & 31;
    if (n >= NN) return;
    size_t base = (size_t)n * HID + l * 4;

    float4 p = *(const float4*)(g_proj + base);
    float4 xx = *(const float4*)(x + base);
    float4 b = *(const float4*)(pb + l * 4);
    float4 h;
    h.x = p.x + b.x + xx.x;
    h.y = p.y + b.y + xx.y;
    h.z = p.z + b.z + xx.z;
    h.w = p.w + b.w + xx.w;

    float s = h.x + h.y + h.z + h.w;
    #pragma unroll
    for (int off = 16; off >= 1; off >>= 1) s += __shfl_xor_sync(0xFFFFFFFFu, s, off);
    float mu = s * (1.0f / HID);

    float dx = h.x - mu, dy = h.y - mu, dz = h.z - mu, dw = h.w - mu;
    float v = dx * dx + dy * dy + dz * dz + dw * dw;
    #pragma unroll
    for (int off = 16; off >= 1; off >>= 1) v += __shfl_xor_sync(0xFFFFFFFFu, v, off);
    float inv = rsqrtf(v * (1.0f / HID) + LN_EPS);

    float4 g = *(const float4*)(gamma + l * 4);
    float4 be = *(const float4*)(beta + l * 4);
    float4 o;
    o.x = dx * inv * g.x + be.x;
    o.y = dy * inv * g.y + be.y;
    o.z = dz * inv * g.z + be.z;
    o.w = dw * inv * g.w + be.w;
    *(float4*)(out + base) = o;
}

// ---------------- launch ----------------
extern "C" void kernel_launch(void* const* d_in, const int* in_sizes, int n_in,
                              void* d_out, int out_size) {
    const float* x     = (const float*)d_in[0];
    const int*   ei    = (const int*)d_in[1];   // int32 or packed int64 (auto-detected)
    const int*   et    = (const int*)d_in[2];
    const float* WQ    = (const float*)d_in[3];
    const float* WK    = (const float*)d_in[4];
    const float* WV    = (const float*)d_in[5];
    const float* bias  = (const float*)d_in[6];
    const float* Wp    = (const float*)d_in[7];
    const float* pb    = (const float*)d_in[8];
    const float* gamma = (const float*)d_in[9];
    const float* beta  = (const float*)d_in[10];
    float* out = (float*)d_out;

    detect_kernel<<<1, 32>>>(ei);
    convert_kernel<<<(EE + 255) / 256, 256>>>(ei, et);
    zero_kernel<<<1024, 256>>>();
    repack_kernel<<<(HID * NCOLS + 255) / 256, 256>>>(WQ, WK, WV, Wp);

    // counting sort of edges by dst
    hist_kernel<<<(EE + 255) / 256, 256>>>();
    scan_kernel<<<1, 1024>>>();
    scatter_kernel<<<(EE + 255) / 256, 256>>>();

    dim3 g1(NN_PAD / 128, NCOLS / 128);       // 391 x 15
    gemm_qkv_kernel<<<g1, 256>>>(x);

    int edge_blocks = (EE * 32 + 255) / 256;  // 80000
    edge_logits_kernel<<<edge_blocks, 256>>>(bias);

    int seg_blocks = (NN * 32 + 255) / 256;   // 6250
    seg_accum_kernel<<<seg_blocks, 256>>>();

    dim3 g2(NN_PAD / 128, 1);                 // 391 x 1
    gemm_proj_kernel<<<g2, 256>>>();

    int ln_blocks = (NN * 32 + 255) / 256;    // 6250
    ln_kernel<<<ln_blocks, 256>>>(x, pb, gamma, beta, out);
}